// round 16
// baseline (speedup 1.0000x reference)
#include <cuda_runtime.h>
#include <cuda_fp16.h>
#include <cstdint>

#define N_NODES 100000
#define D 128
#define E_EDGES 640000

#define MTILE 128
#define NBLK 782                 // 782 * 128 = 100096
#define NSM 148

#define CAP 40
#define OVF_MAX 4096

#define RB 272
#define T_BYTES (128 * RB)          // 34816 per tile

__device__ int   g_cnt[N_NODES];     // zeroed by previous replay's MLP kernel
__device__ int   g_list[(size_t)N_NODES * CAP];
__device__ int   g_ovf_cnt;
__device__ int2  g_ovf[OVF_MAX];
__device__ __align__(16) uint8_t g_Hh[(size_t)NBLK * T_BYTES];  // fp16 H tiles
__device__ __align__(16) uint8_t g_Wprep[2 * T_BYTES];

#define SM_A0  0
#define SM_A1  (T_BYTES)
#define SM_W1  (2 * T_BYTES)
#define SM_W2  (3 * T_BYTES)
#define SM_B1  (4 * T_BYTES)
#define SM_B2  (4 * T_BYTES + 512)
#define SM_TOTAL (4 * T_BYTES + 1024)   // 140288

#define MLP_T 256                       // 8 warps, warp tile 16m x 128n
#define NB_EDGE 625                     // 160000 edge threads (4 edges each)
#define NB_W    64                      // 16384 W threads

// ---------------------------------------------------------------------------
__device__ __forceinline__ uint32_t smem_u32(const void* p) {
    uint32_t a;
    asm("{ .reg .u64 t; cvta.to.shared.u64 t, %1; cvt.u32.u64 %0, t; }"
        : "=r"(a) : "l"(p));
    return a;
}
#define CP_ASYNC16(saddr, gptr) \
    asm volatile("cp.async.cg.shared.global [%0], [%1], 16;" \
        :: "r"(saddr), "l"(gptr) : "memory")
#define CP_COMMIT() asm volatile("cp.async.commit_group;" ::: "memory")
#define CP_WAIT0()  asm volatile("cp.async.wait_group 0;" ::: "memory")

#define LDSM_X4(r0, r1, r2, r3, addr) \
    asm volatile("ldmatrix.sync.aligned.m8n8.x4.shared.b16 {%0,%1,%2,%3}, [%4];" \
        : "=r"(r0), "=r"(r1), "=r"(r2), "=r"(r3) : "r"(addr))

__device__ __forceinline__ void mma_f16(float* d, const uint32_t* a,
                                        uint32_t b0, uint32_t b1) {
    asm volatile(
        "mma.sync.aligned.m16n8k16.row.col.f32.f16.f16.f32 "
        "{%0,%1,%2,%3}, {%4,%5,%6,%7}, {%8,%9}, {%0,%1,%2,%3};"
        : "+f"(d[0]), "+f"(d[1]), "+f"(d[2]), "+f"(d[3])
        : "r"(a[0]), "r"(a[1]), "r"(a[2]), "r"(a[3]), "r"(b0), "r"(b1));
}
__device__ __forceinline__ uint32_t packh2(float a, float b) {
    __half2 p = __floats2half2_rn(a, b);
    return *(uint32_t*)&p;
}

// ---------------------------------------------------------------------------
// Kernel A: edge bucketing (4 edges/thread) + W-prep (disjoint blocks).
// No x traffic at all — gather reads fp32 x directly.
// ---------------------------------------------------------------------------
__global__ void __launch_bounds__(256)
place_kernel(const float* __restrict__ W1, const float* __restrict__ W2,
             const int* __restrict__ ei) {
    const int b = blockIdx.x;
    const int tid = threadIdx.x;
    if (b < NB_EDGE) {
        int ie = b * 256 + tid;                 // < 160000
        int4 rr = *(const int4*)(ei + 4 * ie);             // sources
        int4 cc = *(const int4*)(ei + E_EDGES + 4 * ie);   // destinations
        int r[4] = {rr.x, rr.y, rr.z, rr.w};
        int c[4] = {cc.x, cc.y, cc.z, cc.w};
        #pragma unroll
        for (int u = 0; u < 4; u++) {
            int p = atomicAdd(&g_cnt[c[u]], 1);
            if (p < CAP) {
                g_list[(size_t)c[u] * CAP + p] = r[u];
            } else {
                int q = atomicAdd(&g_ovf_cnt, 1);
                if (q < OVF_MAX) g_ovf[q] = make_int2(r[u], c[u]);
            }
        }
        return;
    }
    int iw = (b - NB_EDGE) * 256 + tid;         // < 16384
    if (iw < D * D) {
        int k = iw >> 7, n = iw & 127;
        uint32_t so = (uint32_t)(n * RB + (k >> 3) * 16 + (k & 7) * 2);
        *(__half*)(g_Wprep + so)           = __float2half_rn(W1[iw]);
        *(__half*)(g_Wprep + T_BYTES + so) = __float2half_rn(W2[iw]);
    }
}

// ---------------------------------------------------------------------------
// Kernel B: gather from fp32 x (no pre-conversion). One warp per node; lane
// owns a float4 (4 dims). MLP=4. fp32 accumulation; fp16 swizzled H out.
// ---------------------------------------------------------------------------
__global__ void __launch_bounds__(256)
gather_kernel(const float* __restrict__ x) {
    int gw = (blockIdx.x * blockDim.x + threadIdx.x) >> 5;
    int lane = threadIdx.x & 31;
    if (gw >= N_NODES) return;
    int cnt0 = g_cnt[gw];
    int cnt = cnt0 > CAP ? CAP : cnt0;
    const float4* xr = (const float4*)x;

    float4 a0 = __ldg(&xr[(size_t)gw * 32 + lane]);
    float4 a1 = make_float4(0.f, 0.f, 0.f, 0.f);
    float4 a2 = make_float4(0.f, 0.f, 0.f, 0.f);
    float4 a3 = make_float4(0.f, 0.f, 0.f, 0.f);

    int mysrc = (lane < cnt) ? g_list[(size_t)gw * CAP + lane] : 0;
    int c2 = cnt < 32 ? cnt : 32;
    int i = 0;
    for (; i + 4 <= c2; i += 4) {
        int s0 = __shfl_sync(0xffffffffu, mysrc, i);
        int s1 = __shfl_sync(0xffffffffu, mysrc, i + 1);
        int s2 = __shfl_sync(0xffffffffu, mysrc, i + 2);
        int s3 = __shfl_sync(0xffffffffu, mysrc, i + 3);
        float4 v0 = __ldg(&xr[(size_t)s0 * 32 + lane]);
        float4 v1 = __ldg(&xr[(size_t)s1 * 32 + lane]);
        float4 v2 = __ldg(&xr[(size_t)s2 * 32 + lane]);
        float4 v3 = __ldg(&xr[(size_t)s3 * 32 + lane]);
        a0.x += v0.x; a0.y += v0.y; a0.z += v0.z; a0.w += v0.w;
        a1.x += v1.x; a1.y += v1.y; a1.z += v1.z; a1.w += v1.w;
        a2.x += v2.x; a2.y += v2.y; a2.z += v2.z; a2.w += v2.w;
        a3.x += v3.x; a3.y += v3.y; a3.z += v3.z; a3.w += v3.w;
    }
    for (; i < c2; i++) {
        int s = __shfl_sync(0xffffffffu, mysrc, i);
        float4 v = __ldg(&xr[(size_t)s * 32 + lane]);
        a0.x += v.x; a0.y += v.y; a0.z += v.z; a0.w += v.w;
    }
    for (int j = 32; j < cnt; j++) {
        int s = g_list[(size_t)gw * CAP + j];
        float4 v = __ldg(&xr[(size_t)s * 32 + lane]);
        a0.x += v.x; a0.y += v.y; a0.z += v.z; a0.w += v.w;
    }
    if (cnt0 > CAP) {
        int n = g_ovf_cnt; if (n > OVF_MAX) n = OVF_MAX;
        for (int e = 0; e < n; e++) {
            int2 ed = g_ovf[e];
            if (ed.y == gw) {
                float4 v = __ldg(&xr[(size_t)ed.x * 32 + lane]);
                a0.x += v.x; a0.y += v.y; a0.z += v.z; a0.w += v.w;
            }
        }
    }
    float fx = (a0.x + a1.x) + (a2.x + a3.x);
    float fy = (a0.y + a1.y) + (a2.y + a3.y);
    float fz = (a0.z + a1.z) + (a2.z + a3.z);
    float fw = (a0.w + a1.w) + (a2.w + a3.w);

    int t = gw >> 7, row = gw & 127;
    uint32_t so = (uint32_t)(row * RB + (lane >> 1) * 16 + (lane & 1) * 8);
    uint2 p;
    p.x = packh2(fx, fy);
    p.y = packh2(fz, fw);
    *(uint2*)(g_Hh + (size_t)t * T_BYTES + so) = p;
}

// ---------------------------------------------------------------------------
// Kernel C: persistent fp16 MLP, 8 warps, m16 x n128 warp tiles, register
// C-frag -> A-frag epilogue.  (R13-proven, unchanged)
// ---------------------------------------------------------------------------
__global__ void __launch_bounds__(MLP_T, 1)
mlp_mma_kernel(const float* __restrict__ b1, const float* __restrict__ b2,
               float* __restrict__ out) {
    extern __shared__ char smem[];
    const uint32_t sb = smem_u32(smem);
    const int tid = threadIdx.x;
    const int lane = tid & 31;
    const int wid = tid >> 5;          // 0..7
    const int m0 = wid * 16;

    {
        const char* wg = (const char*)g_Wprep;
        #pragma unroll 4
        for (int i = tid; i < 2 * T_BYTES / 16; i += MLP_T)
            CP_ASYNC16(sb + SM_W1 + i * 16, wg + i * 16);
        const char* hg = (const char*)(g_Hh + (size_t)blockIdx.x * T_BYTES);
        #pragma unroll 4
        for (int i = tid; i < T_BYTES / 16; i += MLP_T)
            CP_ASYNC16(sb + SM_A0 + i * 16, hg + i * 16);
    }
    CP_COMMIT();

    // re-zero counters for the next graph replay
    {
        int gt = blockIdx.x * MLP_T + tid;
        int4* c4 = (int4*)g_cnt;
        for (int i = gt; i < N_NODES / 4; i += NSM * MLP_T)
            c4[i] = make_int4(0, 0, 0, 0);
        if (gt == 0) g_ovf_cnt = 0;
    }
    if (tid < 128) {
        ((float*)(smem + SM_B1))[tid] = b1[tid];
        ((float*)(smem + SM_B2))[tid] = b2[tid];
    }

    const int li = lane & 7;
    const int sub = lane >> 3;
    const uint32_t a_off = (uint32_t)((m0 + li + (sub & 1) * 8) * RB + (sub >> 1) * 16);
    const uint32_t b_off = (uint32_t)((li + (sub >> 1) * 8) * RB + (sub & 1) * 16);
    const int cbase = 2 * (lane & 3);
    const int gid = lane >> 2;

    int cur = 0;
    for (int t = blockIdx.x; t < NBLK; t += NSM) {
        CP_WAIT0();
        __syncthreads();

        int tn = t + NSM;
        if (tn < NBLK) {
            uint32_t dst = sb + (cur ? SM_A0 : SM_A1);
            const char* hg = (const char*)(g_Hh + (size_t)tn * T_BYTES);
            #pragma unroll 4
            for (int i = tid; i < T_BYTES / 16; i += MLP_T)
                CP_ASYNC16(dst + i * 16, hg + i * 16);
        }
        CP_COMMIT();

        const uint32_t a_t = cur ? SM_A1 : SM_A0;
        float acc[16][4];
        #pragma unroll
        for (int ni = 0; ni < 16; ni++)
            #pragma unroll
            for (int q = 0; q < 4; q++) acc[ni][q] = 0.0f;

        // GEMM1
        #pragma unroll
        for (int ks = 0; ks < 8; ks++) {
            uint32_t ah[4];
            LDSM_X4(ah[0], ah[1], ah[2], ah[3], sb + a_t + a_off + ks * 32);
            #pragma unroll
            for (int nj = 0; nj < 8; nj++) {
                uint32_t r0, r1, r2, r3;
                LDSM_X4(r0, r1, r2, r3,
                        sb + SM_W1 + b_off + (uint32_t)(nj * 16 * RB) + ks * 32);
                mma_f16(acc[2 * nj],     ah, r0, r1);
                mma_f16(acc[2 * nj + 1], ah, r2, r3);
            }
        }

        // epilogue1 in registers: relu(+b1), C-frag -> A-frag
        uint32_t af[8][4];
        {
            const float* b1s = (const float*)(smem + SM_B1);
            #pragma unroll
            for (int ni = 0; ni < 16; ni++) {
                float2 bb = *(const float2*)(b1s + ni * 8 + cbase);
                acc[ni][0] = fmaxf(acc[ni][0] + bb.x, 0.0f);
                acc[ni][1] = fmaxf(acc[ni][1] + bb.y, 0.0f);
                acc[ni][2] = fmaxf(acc[ni][2] + bb.x, 0.0f);
                acc[ni][3] = fmaxf(acc[ni][3] + bb.y, 0.0f);
            }
            #pragma unroll
            for (int j = 0; j < 8; j++) {
                af[j][0] = packh2(acc[2 * j][0],     acc[2 * j][1]);
                af[j][1] = packh2(acc[2 * j][2],     acc[2 * j][3]);
                af[j][2] = packh2(acc[2 * j + 1][0], acc[2 * j + 1][1]);
                af[j][3] = packh2(acc[2 * j + 1][2], acc[2 * j + 1][3]);
            }
        }

        #pragma unroll
        for (int ni = 0; ni < 16; ni++)
            #pragma unroll
            for (int q = 0; q < 4; q++) acc[ni][q] = 0.0f;

        // GEMM2 (A from registers)
        #pragma unroll
        for (int j = 0; j < 8; j++) {
            #pragma unroll
            for (int nj = 0; nj < 8; nj++) {
                uint32_t r0, r1, r2, r3;
                LDSM_X4(r0, r1, r2, r3,
                        sb + SM_W2 + b_off + (uint32_t)(nj * 16 * RB) + j * 32);
                mma_f16(acc[2 * nj],     af[j], r0, r1);
                mma_f16(acc[2 * nj + 1], af[j], r2, r3);
            }
        }

        // epilogue2
        {
            const float* b2s = (const float*)(smem + SM_B2);
            int gr0 = t * MTILE + m0 + gid;
            int gr1 = gr0 + 8;
            #pragma unroll
            for (int ni = 0; ni < 16; ni++) {
                int c0 = ni * 8 + cbase;
                float2 bb = *(const float2*)(b2s + c0);
                if (gr0 < N_NODES) {
                    float2 v = make_float2(acc[ni][0] + bb.x, acc[ni][1] + bb.y);
                    *(float2*)(out + (size_t)gr0 * D + c0) = v;
                }
                if (gr1 < N_NODES) {
                    float2 v = make_float2(acc[ni][2] + bb.x, acc[ni][3] + bb.y);
                    *(float2*)(out + (size_t)gr1 * D + c0) = v;
                }
            }
        }
        cur ^= 1;
    }
}

// ---------------------------------------------------------------------------
extern "C" void kernel_launch(void* const* d_in, const int* in_sizes, int n_in,
                              void* d_out, int out_size) {
    const float* x  = (const float*)d_in[0];
    const int*   ei = (const int*)d_in[1];
    const float* W1 = (const float*)d_in[2];
    const float* b1 = (const float*)d_in[3];
    const float* W2 = (const float*)d_in[4];
    const float* b2 = (const float*)d_in[5];
    float*       out = (float*)d_out;

    place_kernel<<<NB_EDGE + NB_W, 256>>>(W1, W2, ei);
    gather_kernel<<<(N_NODES * 32 + 255) / 256, 256>>>(x);
    {
        cudaFuncSetAttribute(mlp_mma_kernel,
                             cudaFuncAttributeMaxDynamicSharedMemorySize, SM_TOTAL);
        mlp_mma_kernel<<<NSM, MLP_T, SM_TOTAL>>>(b1, b2, out);
    }
}

// round 17
// speedup vs baseline: 1.1774x; 1.1774x over previous
#include <cuda_runtime.h>
#include <cuda_fp16.h>
#include <cstdint>

#define N_NODES 100000
#define D 128
#define E_EDGES 640000

#define MTILE 128
#define NBLK 782                 // 782 * 128 = 100096
#define NSM 148

#define CAP 40
#define OVF_MAX 4096

#define RB 272
#define T_BYTES (128 * RB)          // 34816 per tile

__device__ int   g_cnt[N_NODES];     // zeroed by previous replay's MLP kernel
__device__ int   g_list[(size_t)N_NODES * CAP];
__device__ int   g_ovf_cnt;
__device__ int2  g_ovf[OVF_MAX];
__device__ __align__(16) __half g_xh[(size_t)N_NODES * D];
__device__ __align__(16) uint8_t g_Hh[(size_t)NBLK * T_BYTES];
__device__ __align__(16) uint8_t g_Wprep[2 * T_BYTES];

#define SM_A0  0
#define SM_A1  (T_BYTES)
#define SM_W1  (2 * T_BYTES)
#define SM_W2  (3 * T_BYTES)
#define SM_B1  (4 * T_BYTES)
#define SM_B2  (4 * T_BYTES + 512)
#define SM_TOTAL (4 * T_BYTES + 1024)   // 140288

#define MLP_T 256                       // 8 warps, warp tile 16m x 128n
#define PREP_T 400000                   // x-convert threads (8 float4 each)
#define TOTAL_T (PREP_T + E_EDGES + D * D)

// ---------------------------------------------------------------------------
__device__ __forceinline__ uint32_t smem_u32(const void* p) {
    uint32_t a;
    asm("{ .reg .u64 t; cvta.to.shared.u64 t, %1; cvt.u32.u64 %0, t; }"
        : "=r"(a) : "l"(p));
    return a;
}
#define CP_ASYNC16(saddr, gptr) \
    asm volatile("cp.async.cg.shared.global [%0], [%1], 16;" \
        :: "r"(saddr), "l"(gptr) : "memory")
#define CP_COMMIT() asm volatile("cp.async.commit_group;" ::: "memory")
#define CP_WAIT0()  asm volatile("cp.async.wait_group 0;" ::: "memory")

#define LDSM_X4(r0, r1, r2, r3, addr) \
    asm volatile("ldmatrix.sync.aligned.m8n8.x4.shared.b16 {%0,%1,%2,%3}, [%4];" \
        : "=r"(r0), "=r"(r1), "=r"(r2), "=r"(r3) : "r"(addr))

__device__ __forceinline__ void mma_f16(float* d, const uint32_t* a,
                                        uint32_t b0, uint32_t b1) {
    asm volatile(
        "mma.sync.aligned.m16n8k16.row.col.f32.f16.f16.f32 "
        "{%0,%1,%2,%3}, {%4,%5,%6,%7}, {%8,%9}, {%0,%1,%2,%3};"
        : "+f"(d[0]), "+f"(d[1]), "+f"(d[2]), "+f"(d[3])
        : "r"(a[0]), "r"(a[1]), "r"(a[2]), "r"(a[3]), "r"(b0), "r"(b1));
}
__device__ __forceinline__ uint32_t packh2(float a, float b) {
    __half2 p = __floats2half2_rn(a, b);
    return *(uint32_t*)&p;
}
__device__ __forceinline__ void addh2(float& a, float& b, uint32_t p) {
    float2 f = __half22float2(*(__half2*)&p);
    a += f.x; b += f.y;
}
__device__ __forceinline__ void fmah2(float& a, float& b, uint32_t p, float m) {
    float2 f = __half22float2(*(__half2*)&p);
    a = fmaf(f.x, m, a); b = fmaf(f.y, m, b);
}

// ---------------------------------------------------------------------------
// Kernel A: prep + place (R13 structure; edges now 1/thread to remove the
// serialized 4-atomic dependency chain).
//   [0, PREP_T)                    : x -> fp16 (8 float4 per thread)
//   [PREP_T, PREP_T+E_EDGES)       : edge bucketing, 1 edge/thread
//   [PREP_T+E_EDGES, +D*D)         : W -> fp16 swizzled
// ---------------------------------------------------------------------------
__global__ void __launch_bounds__(256)
prep_place_kernel(const float* __restrict__ x,
                  const float* __restrict__ W1,
                  const float* __restrict__ W2,
                  const int* __restrict__ ei) {
    int i = blockIdx.x * blockDim.x + threadIdx.x;

    if (i < PREP_T) {
        const float4* xs = (const float4*)x;
        float4 v[8];
        #pragma unroll
        for (int q = 0; q < 4; q++) {
            v[2 * q]     = xs[q * 2 * PREP_T + 2 * i];
            v[2 * q + 1] = xs[q * 2 * PREP_T + 2 * i + 1];
        }
        uint4* xd = (uint4*)g_xh;
        #pragma unroll
        for (int q = 0; q < 4; q++) {
            uint4 p;
            p.x = packh2(v[2 * q].x,     v[2 * q].y);
            p.y = packh2(v[2 * q].z,     v[2 * q].w);
            p.z = packh2(v[2 * q + 1].x, v[2 * q + 1].y);
            p.w = packh2(v[2 * q + 1].z, v[2 * q + 1].w);
            xd[q * PREP_T + i] = p;
        }
        return;
    }
    int ie = i - PREP_T;
    if (ie < E_EDGES) {
        int r = ei[ie];              // source
        int c = ei[E_EDGES + ie];    // destination
        int p = atomicAdd(&g_cnt[c], 1);
        if (p < CAP) {
            g_list[(size_t)c * CAP + p] = r;
        } else {
            int q = atomicAdd(&g_ovf_cnt, 1);
            if (q < OVF_MAX) g_ovf[q] = make_int2(r, c);
        }
        return;
    }
    int iw = ie - E_EDGES;
    if (iw < D * D) {
        int k = iw >> 7, n = iw & 127;
        uint32_t so = (uint32_t)(n * RB + (k >> 3) * 16 + (k & 7) * 2);
        *(__half*)(g_Wprep + so)           = __float2half_rn(W1[iw]);
        *(__half*)(g_Wprep + T_BYTES + so) = __float2half_rn(W2[iw]);
    }
}

// ---------------------------------------------------------------------------
// Kernel B: gather from fp16 x. One warp per node; lane owns 4 dims (8B).
// First 8 neighbors handled BRANCHLESS (safe-index + fp mask, 8 loads in
// flight); remainder (P(deg>8)~0.2) falls back to the 4-wide loop.
// ---------------------------------------------------------------------------
__global__ void __launch_bounds__(256)
gather_kernel() {
    int gw = (blockIdx.x * blockDim.x + threadIdx.x) >> 5;
    int lane = threadIdx.x & 31;
    if (gw >= N_NODES) return;
    int cnt0 = g_cnt[gw];
    int cnt = cnt0 > CAP ? CAP : cnt0;
    const uint2* xr = (const uint2*)g_xh;

    uint2 own = __ldg(&xr[(size_t)gw * 32 + lane]);
    float ax0 = 0.f, ay0 = 0.f, az0 = 0.f, aw0 = 0.f;
    float ax1 = 0.f, ay1 = 0.f, az1 = 0.f, aw1 = 0.f;
    float ax2 = 0.f, ay2 = 0.f, az2 = 0.f, aw2 = 0.f;
    float ax3 = 0.f, ay3 = 0.f, az3 = 0.f, aw3 = 0.f;
    addh2(ax0, ay0, own.x); addh2(az0, aw0, own.y);

    int mysrc = (lane < cnt) ? g_list[(size_t)gw * CAP + lane] : 0;
    int last = cnt > 0 ? cnt - 1 : 0;

    // branchless first-8 batch: all 8 loads issued back-to-back
    {
        int s[8];
        #pragma unroll
        for (int i = 0; i < 8; i++)
            s[i] = __shfl_sync(0xffffffffu, mysrc, i < last ? i : last);
        uint2 v[8];
        #pragma unroll
        for (int i = 0; i < 8; i++)
            v[i] = __ldg(&xr[(size_t)s[i] * 32 + lane]);
        #pragma unroll
        for (int i = 0; i < 8; i++) {
            float m = (i < cnt) ? 1.0f : 0.0f;
            float& fx = (i & 3) == 0 ? ax0 : (i & 3) == 1 ? ax1 : (i & 3) == 2 ? ax2 : ax3;
            float& fy = (i & 3) == 0 ? ay0 : (i & 3) == 1 ? ay1 : (i & 3) == 2 ? ay2 : ay3;
            float& fz = (i & 3) == 0 ? az0 : (i & 3) == 1 ? az1 : (i & 3) == 2 ? az2 : az3;
            float& fw = (i & 3) == 0 ? aw0 : (i & 3) == 1 ? aw1 : (i & 3) == 2 ? aw2 : aw3;
            fmah2(fx, fy, v[i].x, m);
            fmah2(fz, fw, v[i].y, m);
        }
    }
    // remainder (deg > 8)
    int c2 = cnt < 32 ? cnt : 32;
    int i = 8;
    for (; i + 4 <= c2; i += 4) {
        int s0 = __shfl_sync(0xffffffffu, mysrc, i);
        int s1 = __shfl_sync(0xffffffffu, mysrc, i + 1);
        int s2 = __shfl_sync(0xffffffffu, mysrc, i + 2);
        int s3 = __shfl_sync(0xffffffffu, mysrc, i + 3);
        uint2 v0 = __ldg(&xr[(size_t)s0 * 32 + lane]);
        uint2 v1 = __ldg(&xr[(size_t)s1 * 32 + lane]);
        uint2 v2 = __ldg(&xr[(size_t)s2 * 32 + lane]);
        uint2 v3 = __ldg(&xr[(size_t)s3 * 32 + lane]);
        addh2(ax0, ay0, v0.x); addh2(az0, aw0, v0.y);
        addh2(ax1, ay1, v1.x); addh2(az1, aw1, v1.y);
        addh2(ax2, ay2, v2.x); addh2(az2, aw2, v2.y);
        addh2(ax3, ay3, v3.x); addh2(az3, aw3, v3.y);
    }
    for (; i < c2; i++) {
        int s = __shfl_sync(0xffffffffu, mysrc, i);
        uint2 v = __ldg(&xr[(size_t)s * 32 + lane]);
        addh2(ax0, ay0, v.x); addh2(az0, aw0, v.y);
    }
    for (int j = 32; j < cnt; j++) {
        int s = g_list[(size_t)gw * CAP + j];
        uint2 v = __ldg(&xr[(size_t)s * 32 + lane]);
        addh2(ax0, ay0, v.x); addh2(az0, aw0, v.y);
    }
    if (cnt0 > CAP) {
        int n = g_ovf_cnt; if (n > OVF_MAX) n = OVF_MAX;
        for (int e = 0; e < n; e++) {
            int2 ed = g_ovf[e];
            if (ed.y == gw) {
                uint2 v = __ldg(&xr[(size_t)ed.x * 32 + lane]);
                addh2(ax0, ay0, v.x); addh2(az0, aw0, v.y);
            }
        }
    }
    float fx = (ax0 + ax1) + (ax2 + ax3);
    float fy = (ay0 + ay1) + (ay2 + ay3);
    float fz = (az0 + az1) + (az2 + az3);
    float fw = (aw0 + aw1) + (aw2 + aw3);

    int t = gw >> 7, row = gw & 127;
    uint32_t so = (uint32_t)(row * RB + (lane >> 1) * 16 + (lane & 1) * 8);
    uint2 p;
    p.x = packh2(fx, fy);
    p.y = packh2(fz, fw);
    *(uint2*)(g_Hh + (size_t)t * T_BYTES + so) = p;
}

// ---------------------------------------------------------------------------
// Kernel C: persistent fp16 MLP (R13-proven, unchanged).
// ---------------------------------------------------------------------------
__global__ void __launch_bounds__(MLP_T, 1)
mlp_mma_kernel(const float* __restrict__ b1, const float* __restrict__ b2,
               float* __restrict__ out) {
    extern __shared__ char smem[];
    const uint32_t sb = smem_u32(smem);
    const int tid = threadIdx.x;
    const int lane = tid & 31;
    const int wid = tid >> 5;          // 0..7
    const int m0 = wid * 16;

    {
        const char* wg = (const char*)g_Wprep;
        #pragma unroll 4
        for (int i = tid; i < 2 * T_BYTES / 16; i += MLP_T)
            CP_ASYNC16(sb + SM_W1 + i * 16, wg + i * 16);
        const char* hg = (const char*)(g_Hh + (size_t)blockIdx.x * T_BYTES);
        #pragma unroll 4
        for (int i = tid; i < T_BYTES / 16; i += MLP_T)
            CP_ASYNC16(sb + SM_A0 + i * 16, hg + i * 16);
    }
    CP_COMMIT();

    {
        int gt = blockIdx.x * MLP_T + tid;
        int4* c4 = (int4*)g_cnt;
        for (int i = gt; i < N_NODES / 4; i += NSM * MLP_T)
            c4[i] = make_int4(0, 0, 0, 0);
        if (gt == 0) g_ovf_cnt = 0;
    }
    if (tid < 128) {
        ((float*)(smem + SM_B1))[tid] = b1[tid];
        ((float*)(smem + SM_B2))[tid] = b2[tid];
    }

    const int li = lane & 7;
    const int sub = lane >> 3;
    const uint32_t a_off = (uint32_t)((m0 + li + (sub & 1) * 8) * RB + (sub >> 1) * 16);
    const uint32_t b_off = (uint32_t)((li + (sub >> 1) * 8) * RB + (sub & 1) * 16);
    const int cbase = 2 * (lane & 3);
    const int gid = lane >> 2;

    int cur = 0;
    for (int t = blockIdx.x; t < NBLK; t += NSM) {
        CP_WAIT0();
        __syncthreads();

        int tn = t + NSM;
        if (tn < NBLK) {
            uint32_t dst = sb + (cur ? SM_A0 : SM_A1);
            const char* hg = (const char*)(g_Hh + (size_t)tn * T_BYTES);
            #pragma unroll 4
            for (int i = tid; i < T_BYTES / 16; i += MLP_T)
                CP_ASYNC16(dst + i * 16, hg + i * 16);
        }
        CP_COMMIT();

        const uint32_t a_t = cur ? SM_A1 : SM_A0;
        float acc[16][4];
        #pragma unroll
        for (int ni = 0; ni < 16; ni++)
            #pragma unroll
            for (int q = 0; q < 4; q++) acc[ni][q] = 0.0f;

        // GEMM1
        #pragma unroll
        for (int ks = 0; ks < 8; ks++) {
            uint32_t ah[4];
            LDSM_X4(ah[0], ah[1], ah[2], ah[3], sb + a_t + a_off + ks * 32);
            #pragma unroll
            for (int nj = 0; nj < 8; nj++) {
                uint32_t r0, r1, r2, r3;
                LDSM_X4(r0, r1, r2, r3,
                        sb + SM_W1 + b_off + (uint32_t)(nj * 16 * RB) + ks * 32);
                mma_f16(acc[2 * nj],     ah, r0, r1);
                mma_f16(acc[2 * nj + 1], ah, r2, r3);
            }
        }

        // epilogue1 in registers: relu(+b1), C-frag -> A-frag
        uint32_t af[8][4];
        {
            const float* b1s = (const float*)(smem + SM_B1);
            #pragma unroll
            for (int ni = 0; ni < 16; ni++) {
                float2 bb = *(const float2*)(b1s + ni * 8 + cbase);
                acc[ni][0] = fmaxf(acc[ni][0] + bb.x, 0.0f);
                acc[ni][1] = fmaxf(acc[ni][1] + bb.y, 0.0f);
                acc[ni][2] = fmaxf(acc[ni][2] + bb.x, 0.0f);
                acc[ni][3] = fmaxf(acc[ni][3] + bb.y, 0.0f);
            }
            #pragma unroll
            for (int j = 0; j < 8; j++) {
                af[j][0] = packh2(acc[2 * j][0],     acc[2 * j][1]);
                af[j][1] = packh2(acc[2 * j][2],     acc[2 * j][3]);
                af[j][2] = packh2(acc[2 * j + 1][0], acc[2 * j + 1][1]);
                af[j][3] = packh2(acc[2 * j + 1][2], acc[2 * j + 1][3]);
            }
        }

        #pragma unroll
        for (int ni = 0; ni < 16; ni++)
            #pragma unroll
            for (int q = 0; q < 4; q++) acc[ni][q] = 0.0f;

        // GEMM2 (A from registers)
        #pragma unroll
        for (int j = 0; j < 8; j++) {
            #pragma unroll
            for (int nj = 0; nj < 8; nj++) {
                uint32_t r0, r1, r2, r3;
                LDSM_X4(r0, r1, r2, r3,
                        sb + SM_W2 + b_off + (uint32_t)(nj * 16 * RB) + j * 32);
                mma_f16(acc[2 * nj],     af[j], r0, r1);
                mma_f16(acc[2 * nj + 1], af[j], r2, r3);
            }
        }

        // epilogue2
        {
            const float* b2s = (const float*)(smem + SM_B2);
            int gr0 = t * MTILE + m0 + gid;
            int gr1 = gr0 + 8;
            #pragma unroll
            for (int ni = 0; ni < 16; ni++) {
                int c0 = ni * 8 + cbase;
                float2 bb = *(const float2*)(b2s + c0);
                if (gr0 < N_NODES) {
                    float2 v = make_float2(acc[ni][0] + bb.x, acc[ni][1] + bb.y);
                    *(float2*)(out + (size_t)gr0 * D + c0) = v;
                }
                if (gr1 < N_NODES) {
                    float2 v = make_float2(acc[ni][2] + bb.x, acc[ni][3] + bb.y);
                    *(float2*)(out + (size_t)gr1 * D + c0) = v;
                }
            }
        }
        cur ^= 1;
    }
}

// ---------------------------------------------------------------------------
extern "C" void kernel_launch(void* const* d_in, const int* in_sizes, int n_in,
                              void* d_out, int out_size) {
    const float* x  = (const float*)d_in[0];
    const int*   ei = (const int*)d_in[1];
    const float* W1 = (const float*)d_in[2];
    const float* b1 = (const float*)d_in[3];
    const float* W2 = (const float*)d_in[4];
    const float* b2 = (const float*)d_in[5];
    float*       out = (float*)d_out;

    prep_place_kernel<<<(TOTAL_T + 255) / 256, 256>>>(x, W1, W2, ei);
    gather_kernel<<<(N_NODES * 32 + 255) / 256, 256>>>();
    {
        cudaFuncSetAttribute(mlp_mma_kernel,
                             cudaFuncAttributeMaxDynamicSharedMemorySize, SM_TOTAL);
        mlp_mma_kernel<<<NSM, MLP_T, SM_TOTAL>>>(b1, b2, out);
    }
}